// round 10
// baseline (speedup 1.0000x reference)
#include <cuda_runtime.h>
#include <cuda_bf16.h>
#include <math.h>
#include <cstdint>

#define BB 2
#define SS 2048
#define HIDD 1024
#define HH 16
#define DD 64
#define NBH (BB*HH)

// permutation of pair index within its 8-pair group: fragment mates adjacent
#define SIDX(p) (((p) & ~7) + (((p) & 3) << 1) + (((p) >> 2) & 1))

// __device__ scratch (allocation-free rule)
__device__ float2 g_rope[SS*32];          // (cos, sin) per (s, i)
__device__ uint2 gXp[BB*SS*(HIDD/2)];     // X packed (hi,lo) bf16x2 pairs, permuted
__device__ uint2 gWp[3*HIDD*(HIDD/2)];    // Wq,Wk,Wv packed, permuted
__device__ uint2 gQp[NBH*SS*(DD/2)];      // Q roped+scaled, packed, permuted
__device__ uint2 gKp[NBH*SS*(DD/2)];      // K roped, packed, permuted
__device__ uint2 gVt[NBH*DD*(SS/2)];      // V transposed, packed, permuted

// ---------------------------------------------------------------------------
__device__ __forceinline__ uint32_t smem_u32(const void* p) {
    uint32_t a;
    asm("{ .reg .u64 t; cvta.to.shared.u64 t, %1; cvt.u32.u64 %0, t; }" : "=r"(a) : "l"(p));
    return a;
}
__device__ __forceinline__ void cp_async16(uint32_t saddr, const void* gptr) {
    asm volatile("cp.async.cg.shared.global [%0], [%1], 16;"
                 :: "r"(saddr), "l"(__cvta_generic_to_global(gptr)));
}
#define CP_COMMIT() asm volatile("cp.async.commit_group;" ::: "memory")
#define CP_WAIT0()  asm volatile("cp.async.wait_group 0;" ::: "memory")
#define CP_WAIT1()  asm volatile("cp.async.wait_group 1;" ::: "memory")

// split (x,y) -> (hi bf16x2, lo bf16x2)
__device__ __forceinline__ uint2 bsplit(float x, float y) {
    __nv_bfloat162 hb = __float22bfloat162_rn(make_float2(x, y));
    uint32_t h = *(uint32_t*)&hb;
    float hx = __uint_as_float(h << 16);
    float hy = __uint_as_float(h & 0xFFFF0000u);
    __nv_bfloat162 lb = __float22bfloat162_rn(make_float2(x - hx, y - hy));
    return make_uint2(h, *(uint32_t*)&lb);
}
__device__ __forceinline__ void mma_bf16(float c[4],
        uint32_t a0, uint32_t a1, uint32_t a2, uint32_t a3, uint32_t b0, uint32_t b1) {
    asm volatile(
        "mma.sync.aligned.m16n8k16.row.col.f32.bf16.bf16.f32 "
        "{%0,%1,%2,%3}, {%4,%5,%6,%7}, {%8,%9}, {%0,%1,%2,%3};"
        : "+f"(c[0]), "+f"(c[1]), "+f"(c[2]), "+f"(c[3])
        : "r"(a0), "r"(a1), "r"(a2), "r"(a3), "r"(b0), "r"(b1));
}
// 3-term split product: Ah*Bh + Ah*Bl + Al*Bh
__device__ __forceinline__ void mma3v(float c[4], uint4 a01, uint4 a23, uint4 b) {
    mma_bf16(c, a01.x, a23.x, a01.z, a23.z, b.x, b.z);
    mma_bf16(c, a01.x, a23.x, a01.z, a23.z, b.y, b.w);
    mma_bf16(c, a01.y, a23.y, a01.w, a23.w, b.x, b.z);
}

// ---------------------------------------------------------------------------
__global__ __launch_bounds__(256)
void rope_table_kernel()
{
    int idx = blockIdx.x * 256 + threadIdx.x;    // 65536
    int s = idx >> 5, i = idx & 31;
    float inv_freq = exp2f(-(float)i * 0.4152410118609203f);
    float ang = (float)s * inv_freq;
    float k = rintf(ang * 0.15915494309189535f);
    float r = fmaf(-k, 6.2831854820251465f, ang);
    r = fmaf(-k, -1.7484556e-07f, r);
    float sn, cs; __sincosf(r, &sn, &cs);
    g_rope[idx] = make_float2(cs, sn);
}

__global__ __launch_bounds__(256)
void split_pack_kernel(const float* __restrict__ src, uint2* __restrict__ dst, int n4)
{
    int i = blockIdx.x * 256 + threadIdx.x;
    if (i >= n4) return;
    float4 v = ((const float4*)src)[i];
    int P0 = 2 * i, P1 = 2 * i + 1;
    dst[SIDX(P0)] = bsplit(v.x, v.y);
    dst[SIDX(P1)] = bsplit(v.z, v.w);
}

// ---------------------------------------------------------------------------
// QKV GEMM: C = X @ W^T, bf16x3 mma, cp.async double-buffered.
// Fused epilogue: z=0/1 -> RoPE (+0.125 for Q) + split-pack to gQp/gKp;
//                 z=2   -> seq-transpose + split-pack to gVt.
// ---------------------------------------------------------------------------
#define QST 24
#define QK_SMEM (2 * 6144 * (int)sizeof(uint2))

__global__ __launch_bounds__(256, 2)
void qkv_mma_kernel()
{
    extern __shared__ uint2 smu[];
    const int z  = blockIdx.z;
    const uint2* Xg = gXp;
    const uint2* Wg = gWp + (size_t)z * HIDD * (HIDD/2);
    const int bm = blockIdx.x * 128, bn = blockIdx.y * 128;
    const int tid = threadIdx.x, lane = tid & 31, wid = tid >> 5;
    const int warpM = wid & 3, warpN = wid >> 2, g = lane >> 2, t = lane & 3;
    const uint32_t sbase = smem_u32(smu);

    float acc[2][8][4] = {};

    #define QKV_ISSUE(kt, s) do { \
        uint32_t xb = sbase + (uint32_t)((s) * 6144) * 8; \
        _Pragma("unroll") \
        for (int it = 0; it < 4; it++) { \
            int lin = tid + it * 256; \
            int row = lin >> 3, f = (lin & 7) * 2; \
            cp_async16(xb + (row * QST + f) * 8, Xg + (size_t)(bm + row) * 512 + (kt) * 16 + f); \
            cp_async16(xb + (3072 + row * QST + f) * 8, Wg + (size_t)(bn + row) * 512 + (kt) * 16 + f); \
        } \
        CP_COMMIT(); \
    } while (0)

    QKV_ISSUE(0, 0);
    for (int kt = 0; kt < 32; kt++) {
        CP_WAIT0();
        __syncthreads();
        if (kt + 1 < 32) QKV_ISSUE(kt + 1, (kt + 1) & 1);
        const uint2* Xs = smu + (kt & 1) * 6144;
        const uint2* Ws = Xs + 3072;
        #pragma unroll
        for (int ks = 0; ks < 2; ks++) {
            uint4 a01[2], a23[2];
            #pragma unroll
            for (int mt = 0; mt < 2; mt++) {
                int rb = warpM * 32 + mt * 16;
                a01[mt] = *(const uint4*)(Xs + (rb + g)     * QST + ks * 8 + 2 * t);
                a23[mt] = *(const uint4*)(Xs + (rb + g + 8) * QST + ks * 8 + 2 * t);
            }
            #pragma unroll
            for (int nt = 0; nt < 8; nt++) {
                int cb = warpN * 64 + nt * 8;
                uint4 bv = *(const uint4*)(Ws + (cb + g) * QST + ks * 8 + 2 * t);
                mma3v(acc[0][nt], a01[0], a23[0], bv);
                mma3v(acc[1][nt], a01[1], a23[1], bv);
            }
        }
        // no bottom barrier: next issue targets the other stage and happens
        // only after the next top barrier.
    }

    const int h = (bn + warpN * 64) >> 6;
    if (z < 2) {
        const float scl = (z == 0) ? 0.125f : 1.0f;
        uint2* dstb = (z == 0) ? gQp : gKp;
        #pragma unroll
        for (int mt = 0; mt < 2; mt++) {
            #pragma unroll
            for (int half = 0; half < 2; half++) {
                int m  = bm + warpM * 32 + mt * 16 + g + half * 8;
                int b_ = m >> 11, s_ = m & 2047;
                uint2* dst = dstb + ((size_t)((b_ * HH + h) * SS + s_)) * 32;
                float o[4][4];
                #pragma unroll
                for (int nt = 0; nt < 4; nt++) {
                    float4 cs4 = *(const float4*)&g_rope[s_ * 32 + nt * 8 + 2 * t];
                    float x10 = acc[mt][nt][half*2],     x11 = acc[mt][nt][half*2+1];
                    float x20 = acc[mt][nt+4][half*2],   x21 = acc[mt][nt+4][half*2+1];
                    o[nt][0] = (x10 * cs4.x - x20 * cs4.y) * scl;
                    o[nt][1] = (x11 * cs4.z - x21 * cs4.w) * scl;
                    o[nt][2] = (x20 * cs4.x + x10 * cs4.y) * scl;
                    o[nt][3] = (x21 * cs4.z + x11 * cs4.w) * scl;
                }
                uint2 a0, a1;
                a0 = bsplit(o[0][0], o[0][1]); a1 = bsplit(o[1][0], o[1][1]);
                *(uint4*)(dst + 2*t)      = make_uint4(a0.x, a0.y, a1.x, a1.y);
                a0 = bsplit(o[2][0], o[2][1]); a1 = bsplit(o[3][0], o[3][1]);
                *(uint4*)(dst + 8 + 2*t)  = make_uint4(a0.x, a0.y, a1.x, a1.y);
                a0 = bsplit(o[0][2], o[0][3]); a1 = bsplit(o[1][2], o[1][3]);
                *(uint4*)(dst + 16 + 2*t) = make_uint4(a0.x, a0.y, a1.x, a1.y);
                a0 = bsplit(o[2][2], o[2][3]); a1 = bsplit(o[3][2], o[3][3]);
                *(uint4*)(dst + 24 + 2*t) = make_uint4(a0.x, a0.y, a1.x, a1.y);
            }
        }
    } else {
        const bool geven = !(g & 1);
        #pragma unroll
        for (int mt = 0; mt < 2; mt++) {
            int base = bm + warpM * 32 + mt * 16;
            int mp   = geven ? (base + g) : (base + g + 7);
            int b_   = mp >> 11;
            int sp   = (mp & 2047) >> 1;
            size_t rowb = (size_t)((b_ * HH + h) * 64);
            int sidx = SIDX(sp);
            #pragma unroll
            for (int nt = 0; nt < 8; nt++) {
                float c0 = acc[mt][nt][0], c1 = acc[mt][nt][1];
                float c2 = acc[mt][nt][2], c3 = acc[mt][nt][3];
                float p0 = __shfl_xor_sync(0xffffffffu, c0, 4);
                float p1 = __shfl_xor_sync(0xffffffffu, c1, 4);
                float p2 = __shfl_xor_sync(0xffffffffu, c2, 4);
                float p3 = __shfl_xor_sync(0xffffffffu, c3, 4);
                int d0 = nt * 8 + 2 * t;
                uint2 w0 = geven ? bsplit(c0, p0) : bsplit(p2, c2);
                uint2 w1 = geven ? bsplit(c1, p1) : bsplit(p3, c3);
                gVt[(rowb + d0)     * 1024 + sidx] = w0;
                gVt[(rowb + d0 + 1) * 1024 + sidx] = w1;
            }
        }
    }
}

// ---------------------------------------------------------------------------
// Flash attention v3: BM=128, BN=64. 8 warps = 4 warpM (32 rows) x 2 warpN
// (32 keys). Q in smem (loaded once); K/V rotate through 3 smem buffers.
// Partial O / partial l per key-half; cross-warpN reduction at the end.
// Fixed-max softmax (m=0: scores bounded). grid (16, 32).
// ---------------------------------------------------------------------------
#define FST 40
#define QTILE (128 * FST)                 // 5120 uint2
#define KVBUF (64 * FST)                  // 2560 uint2
#define FL_SMEM ((QTILE + 3 * KVBUF) * (int)sizeof(uint2))   // 102400 B

__global__ __launch_bounds__(256, 2)
void flash_kernel(const float* __restrict__ mask, float* __restrict__ out)
{
    extern __shared__ uint2 smu[];
    uint2* Qs = smu;
    uint2* bufs = smu + QTILE;
    const uint32_t sbase = smem_u32(smu);

    const int tid = threadIdx.x, lane = tid & 31, wid = tid >> 5;
    const int g = lane >> 2, t = lane & 3;
    const int warpM = wid & 3, warpN = wid >> 2, wm = warpM * 32;
    const int qt = blockIdx.x, bh = blockIdx.y, b = bh >> 4, h = bh & 15;

    const uint2* Qg = gQp + ((size_t)bh * SS + qt * 128) * 32;
    const uint2* Kg = gKp + (size_t)bh * SS * 32;
    const uint2* Vg = gVt + (size_t)bh * 64 * 1024;
    const float* mb = mask + (size_t)b * SS;

    #define FL_K(kt) do { \
        uint32_t kb = sbase + (uint32_t)(QTILE + ((2*(kt)) % 3) * KVBUF) * 8; \
        _Pragma("unroll") \
        for (int it = 0; it < 4; it++) { \
            int lin = tid + it * 256; \
            int row = lin >> 4, f = (lin & 15) * 2; \
            cp_async16(kb + (row * FST + f) * 8, Kg + (size_t)((kt)*64 + row) * 32 + f); \
        } \
    } while (0)
    #define FL_V(kt) do { \
        uint32_t vb = sbase + (uint32_t)(QTILE + ((2*(kt)+1) % 3) * KVBUF) * 8; \
        _Pragma("unroll") \
        for (int it = 0; it < 4; it++) { \
            int lin = tid + it * 256; \
            int row = lin >> 4, f = (lin & 15) * 2; \
            cp_async16(vb + (row * FST + f) * 8, Vg + (size_t)row * 1024 + (kt) * 32 + f); \
        } \
    } while (0)

    // prologue: group0 = Q + K0, group1 = V0
    #pragma unroll
    for (int it = 0; it < 8; it++) {
        int lin = tid + it * 256;
        int row = lin >> 4, f = (lin & 15) * 2;
        cp_async16(sbase + (uint32_t)(row * FST + f) * 8, Qg + (size_t)row * 32 + f);
    }
    FL_K(0); CP_COMMIT();
    FL_V(0); CP_COMMIT();

    float lp[2][2] = {};
    float oc[2][8][4] = {};

    for (int kt = 0; kt < 32; kt++) {
        CP_WAIT1();                 // K(kt) (and Q) ready
        __syncthreads();
        if (kt + 1 < 32) { FL_K(kt + 1); CP_COMMIT(); }
        const uint2* Ks = bufs + ((2*kt) % 3) * KVBUF;
        const uint2* Vs = bufs + ((2*kt + 1) % 3) * KVBUF;

        // S = Q K^T over this warp's 32 keys
        float sc[2][4][4] = {};
        #pragma unroll
        for (int ks = 0; ks < 4; ks++) {
            uint4 a01[2], a23[2];
            #pragma unroll
            for (int mf = 0; mf < 2; mf++) {
                a01[mf] = *(const uint4*)(Qs + (wm + mf*16 + g)     * FST + ks * 8 + 2 * t);
                a23[mf] = *(const uint4*)(Qs + (wm + mf*16 + g + 8) * FST + ks * 8 + 2 * t);
            }
            #pragma unroll
            for (int nt = 0; nt < 4; nt++) {
                uint4 bv = *(const uint4*)(Ks + (warpN*32 + nt*8 + g) * FST + ks * 8 + 2 * t);
                mma3v(sc[0][nt], a01[0], a23[0], bv);
                mma3v(sc[1][nt], a01[1], a23[1], bv);
            }
        }

        if (kt < 31) { CP_WAIT1(); } else { CP_WAIT0(); }   // V(kt) ready
        __syncthreads();
        if (kt + 1 < 32) { FL_V(kt + 1); CP_COMMIT(); }

        // mask (LDG, L1-resident) + exp, partial l
        #pragma unroll
        for (int nt = 0; nt < 4; nt++) {
            float2 mv = *(const float2*)(mb + kt*64 + warpN*32 + nt*8 + 2*t);
            #pragma unroll
            for (int mf = 0; mf < 2; mf++) {
                sc[mf][nt][0] = __expf(sc[mf][nt][0] + mv.x); lp[mf][0] += sc[mf][nt][0];
                sc[mf][nt][1] = __expf(sc[mf][nt][1] + mv.y); lp[mf][0] += sc[mf][nt][1];
                sc[mf][nt][2] = __expf(sc[mf][nt][2] + mv.x); lp[mf][1] += sc[mf][nt][2];
                sc[mf][nt][3] = __expf(sc[mf][nt][3] + mv.y); lp[mf][1] += sc[mf][nt][3];
            }
        }

        // O += P V (keys split by kf)
        #pragma unroll
        for (int kf = 0; kf < 2; kf++) {
            uint4 a01[2], a23[2];
            #pragma unroll
            for (int mf = 0; mf < 2; mf++) {
                uint2 x0 = bsplit(sc[mf][2*kf][0],   sc[mf][2*kf][1]);
                uint2 x1 = bsplit(sc[mf][2*kf+1][0], sc[mf][2*kf+1][1]);
                a01[mf] = make_uint4(x0.x, x0.y, x1.x, x1.y);
                uint2 y0 = bsplit(sc[mf][2*kf][2],   sc[mf][2*kf][3]);
                uint2 y1 = bsplit(sc[mf][2*kf+1][2], sc[mf][2*kf+1][3]);
                a23[mf] = make_uint4(y0.x, y0.y, y1.x, y1.y);
            }
            #pragma unroll
            for (int dt = 0; dt < 8; dt++) {
                uint4 bv = *(const uint4*)(Vs + (dt*8 + g) * FST + warpN*16 + kf*8 + 2*t);
                mma3v(oc[0][dt], a01[0], a23[0], bv);
                mma3v(oc[1][dt], a01[1], a23[1], bv);
            }
        }
    }

    // cross-warpN reduction: warpN=1 stores partials, warpN=0 combines.
    __syncthreads();
    float* Os  = (float*)smu;            // [128][66]
    float* lps = Os + 128 * 66;          // [128][4]
    if (warpN == 1) {
        #pragma unroll
        for (int mf = 0; mf < 2; mf++) {
            int r0 = wm + mf * 16 + g;
            #pragma unroll
            for (int dt = 0; dt < 8; dt++) {
                *(float2*)&Os[r0 * 66 + dt*8 + 2*t]       = make_float2(oc[mf][dt][0], oc[mf][dt][1]);
                *(float2*)&Os[(r0 + 8) * 66 + dt*8 + 2*t] = make_float2(oc[mf][dt][2], oc[mf][dt][3]);
            }
            lps[r0 * 4 + t]       = lp[mf][0];
            lps[(r0 + 8) * 4 + t] = lp[mf][1];
        }
    }
    __syncthreads();
    if (warpN == 0) {
        #pragma unroll
        for (int mf = 0; mf < 2; mf++) {
            int r0 = wm + mf * 16 + g;
            float l0 = lp[mf][0] + lps[r0 * 4 + t];
            float l1 = lp[mf][1] + lps[(r0 + 8) * 4 + t];
            l0 += __shfl_xor_sync(0xffffffffu, l0, 1);
            l0 += __shfl_xor_sync(0xffffffffu, l0, 2);
            l1 += __shfl_xor_sync(0xffffffffu, l1, 1);
            l1 += __shfl_xor_sync(0xffffffffu, l1, 2);
            float inv0 = 1.0f / l0, inv1 = 1.0f / l1;
            #pragma unroll
            for (int dt = 0; dt < 8; dt++) {
                float2 p0 = *(const float2*)&Os[r0 * 66 + dt*8 + 2*t];
                float2 p1 = *(const float2*)&Os[(r0 + 8) * 66 + dt*8 + 2*t];
                int d = dt * 8 + 2 * t;
                float* baseo = out + ((size_t)(b * SS + qt * 128 + r0)) * HIDD + h * 64 + d;
                *(float2*)baseo = make_float2((oc[mf][dt][0] + p0.x) * inv0,
                                              (oc[mf][dt][1] + p0.y) * inv0);
                *(float2*)(baseo + 8 * HIDD) = make_float2((oc[mf][dt][2] + p1.x) * inv1,
                                                           (oc[mf][dt][3] + p1.y) * inv1);
            }
        }
    }
}

// ---------------------------------------------------------------------------
extern "C" void kernel_launch(void* const* d_in, const int* in_sizes, int n_in,
                              void* d_out, int out_size)
{
    const float* X    = (const float*)d_in[0];
    const float* mask = (const float*)d_in[1];
    const float* Wq   = (const float*)d_in[2];
    const float* Wk   = (const float*)d_in[3];
    const float* Wv   = (const float*)d_in[4];
    float* out = (float*)d_out;

    uint2 *xp, *wp;
    cudaGetSymbolAddress((void**)&xp, gXp);
    cudaGetSymbolAddress((void**)&wp, gWp);

    rope_table_kernel<<<256, 256>>>();
    split_pack_kernel<<<4096, 256>>>(X, xp, BB*SS*HIDD/4);
    split_pack_kernel<<<1024, 256>>>(Wq, wp + 0*HIDD*(HIDD/2), HIDD*HIDD/4);
    split_pack_kernel<<<1024, 256>>>(Wk, wp + 1*HIDD*(HIDD/2), HIDD*HIDD/4);
    split_pack_kernel<<<1024, 256>>>(Wv, wp + 2*HIDD*(HIDD/2), HIDD*HIDD/4);

    cudaFuncSetAttribute(qkv_mma_kernel, cudaFuncAttributeMaxDynamicSharedMemorySize, QK_SMEM);
    qkv_mma_kernel<<<dim3(32, 8, 3), 256, QK_SMEM>>>();

    cudaFuncSetAttribute(flash_kernel, cudaFuncAttributeMaxDynamicSharedMemorySize, FL_SMEM);
    flash_kernel<<<dim3(SS/128, NBH), 256, FL_SMEM>>>(mask, out);
}

// round 11
// speedup vs baseline: 1.1161x; 1.1161x over previous
#include <cuda_runtime.h>
#include <cuda_bf16.h>
#include <math.h>
#include <cstdint>

#define BB 2
#define SS 2048
#define HIDD 1024
#define HH 16
#define DD 64
#define NBH (BB*HH)

// permutation of pair index within its 8-pair group: fragment mates adjacent
#define SIDX(p) (((p) & ~7) + (((p) & 3) << 1) + (((p) >> 2) & 1))

// __device__ scratch (allocation-free rule)
__device__ float2 g_rope[SS*32];          // (cos, sin) per (s, i)
__device__ uint2 gXp[BB*SS*(HIDD/2)];     // X packed (hi,lo) bf16x2 pairs, permuted
__device__ uint2 gWp[3*HIDD*(HIDD/2)];    // Wq,Wk,Wv packed, permuted
__device__ uint2 gQp[NBH*SS*(DD/2)];      // Q roped+scaled, packed, permuted
__device__ uint2 gKp[NBH*SS*(DD/2)];      // K roped, packed, permuted
__device__ uint2 gVt[NBH*DD*(SS/2)];      // V transposed, packed, permuted

// ---------------------------------------------------------------------------
__device__ __forceinline__ uint32_t smem_u32(const void* p) {
    uint32_t a;
    asm("{ .reg .u64 t; cvta.to.shared.u64 t, %1; cvt.u32.u64 %0, t; }" : "=r"(a) : "l"(p));
    return a;
}
__device__ __forceinline__ void cp_async16(uint32_t saddr, const void* gptr) {
    asm volatile("cp.async.cg.shared.global [%0], [%1], 16;"
                 :: "r"(saddr), "l"(__cvta_generic_to_global(gptr)));
}
#define CP_COMMIT() asm volatile("cp.async.commit_group;" ::: "memory")
#define CP_WAIT0()  asm volatile("cp.async.wait_group 0;" ::: "memory")

// split (x,y) -> (hi bf16x2, lo bf16x2)
__device__ __forceinline__ uint2 bsplit(float x, float y) {
    __nv_bfloat162 hb = __float22bfloat162_rn(make_float2(x, y));
    uint32_t h = *(uint32_t*)&hb;
    float hx = __uint_as_float(h << 16);
    float hy = __uint_as_float(h & 0xFFFF0000u);
    __nv_bfloat162 lb = __float22bfloat162_rn(make_float2(x - hx, y - hy));
    return make_uint2(h, *(uint32_t*)&lb);
}
__device__ __forceinline__ void mma_bf16(float c[4],
        uint32_t a0, uint32_t a1, uint32_t a2, uint32_t a3, uint32_t b0, uint32_t b1) {
    asm volatile(
        "mma.sync.aligned.m16n8k16.row.col.f32.bf16.bf16.f32 "
        "{%0,%1,%2,%3}, {%4,%5,%6,%7}, {%8,%9}, {%0,%1,%2,%3};"
        : "+f"(c[0]), "+f"(c[1]), "+f"(c[2]), "+f"(c[3])
        : "r"(a0), "r"(a1), "r"(a2), "r"(a3), "r"(b0), "r"(b1));
}
// 3-term split product: Ah*Bh + Ah*Bl + Al*Bh
__device__ __forceinline__ void mma3v(float c[4], uint4 a01, uint4 a23, uint4 b) {
    mma_bf16(c, a01.x, a23.x, a01.z, a23.z, b.x, b.z);
    mma_bf16(c, a01.x, a23.x, a01.z, a23.z, b.y, b.w);
    mma_bf16(c, a01.y, a23.y, a01.w, a23.w, b.x, b.z);
}

// ---------------------------------------------------------------------------
__global__ __launch_bounds__(256)
void rope_table_kernel()
{
    int idx = blockIdx.x * 256 + threadIdx.x;    // 65536
    int s = idx >> 5, i = idx & 31;
    float inv_freq = exp2f(-(float)i * 0.4152410118609203f);
    float ang = (float)s * inv_freq;
    float k = rintf(ang * 0.15915494309189535f);
    float r = fmaf(-k, 6.2831854820251465f, ang);
    r = fmaf(-k, -1.7484556e-07f, r);
    float sn, cs; __sincosf(r, &sn, &cs);
    g_rope[idx] = make_float2(cs, sn);
}

// split X (f32) -> packed (hi,lo) bf16x2 pairs, permuted store
__global__ __launch_bounds__(256)
void split_pack_kernel(const float* __restrict__ src, uint2* __restrict__ dst, int n4)
{
    int i = blockIdx.x * 256 + threadIdx.x;
    if (i >= n4) return;
    float4 v = ((const float4*)src)[i];
    dst[SIDX(2*i)]   = bsplit(v.x, v.y);
    dst[SIDX(2*i+1)] = bsplit(v.z, v.w);
}

// split all three W matrices in one launch (grid.y selects the source)
__global__ __launch_bounds__(256)
void split_pack_w_kernel(const float* __restrict__ Wq,
                         const float* __restrict__ Wk,
                         const float* __restrict__ Wv)
{
    const float* src = (blockIdx.y == 0) ? Wq : (blockIdx.y == 1) ? Wk : Wv;
    uint2* dst = gWp + (size_t)blockIdx.y * HIDD * (HIDD/2);
    int i = blockIdx.x * 256 + threadIdx.x;      // 262144 float4s
    float4 v = ((const float4*)src)[i];
    dst[SIDX(2*i)]   = bsplit(v.x, v.y);
    dst[SIDX(2*i+1)] = bsplit(v.z, v.w);
}

// ---------------------------------------------------------------------------
// QKV GEMM: C = X @ W^T, bf16x3 mma, cp.async double-buffered.
// Fused epilogue: z=0/1 -> RoPE (+0.125 for Q) + split-pack to gQp/gKp;
//                 z=2   -> seq-transpose + split-pack to gVt.
// ---------------------------------------------------------------------------
#define QST 24
#define QK_SMEM (2 * 6144 * (int)sizeof(uint2))

__global__ __launch_bounds__(256, 2)
void qkv_mma_kernel()
{
    extern __shared__ uint2 smu[];
    const int z  = blockIdx.z;
    const uint2* Xg = gXp;
    const uint2* Wg = gWp + (size_t)z * HIDD * (HIDD/2);
    const int bm = blockIdx.x * 128, bn = blockIdx.y * 128;
    const int tid = threadIdx.x, lane = tid & 31, wid = tid >> 5;
    const int warpM = wid & 3, warpN = wid >> 2, g = lane >> 2, t = lane & 3;
    const uint32_t sbase = smem_u32(smu);

    float acc[2][8][4] = {};

    #define QKV_ISSUE(kt, s) do { \
        uint32_t xb = sbase + (uint32_t)((s) * 6144) * 8; \
        _Pragma("unroll") \
        for (int it = 0; it < 4; it++) { \
            int lin = tid + it * 256; \
            int row = lin >> 3, f = (lin & 7) * 2; \
            cp_async16(xb + (row * QST + f) * 8, Xg + (size_t)(bm + row) * 512 + (kt) * 16 + f); \
            cp_async16(xb + (3072 + row * QST + f) * 8, Wg + (size_t)(bn + row) * 512 + (kt) * 16 + f); \
        } \
        CP_COMMIT(); \
    } while (0)

    QKV_ISSUE(0, 0);
    for (int kt = 0; kt < 32; kt++) {
        CP_WAIT0();
        __syncthreads();
        if (kt + 1 < 32) QKV_ISSUE(kt + 1, (kt + 1) & 1);
        const uint2* Xs = smu + (kt & 1) * 6144;
        const uint2* Ws = Xs + 3072;
        #pragma unroll
        for (int ks = 0; ks < 2; ks++) {
            uint4 a01[2], a23[2];
            #pragma unroll
            for (int mt = 0; mt < 2; mt++) {
                int rb = warpM * 32 + mt * 16;
                a01[mt] = *(const uint4*)(Xs + (rb + g)     * QST + ks * 8 + 2 * t);
                a23[mt] = *(const uint4*)(Xs + (rb + g + 8) * QST + ks * 8 + 2 * t);
            }
            #pragma unroll
            for (int nt = 0; nt < 8; nt++) {
                int cb = warpN * 64 + nt * 8;
                uint4 bv = *(const uint4*)(Ws + (cb + g) * QST + ks * 8 + 2 * t);
                mma3v(acc[0][nt], a01[0], a23[0], bv);
                mma3v(acc[1][nt], a01[1], a23[1], bv);
            }
        }
        // no bottom barrier: the next issue targets the other stage, and only
        // happens after the next top barrier (all warps past compute here).
    }

    const int h = (bn + warpN * 64) >> 6;
    if (z < 2) {
        const float scl = (z == 0) ? 0.125f : 1.0f;
        uint2* dstb = (z == 0) ? gQp : gKp;
        #pragma unroll
        for (int mt = 0; mt < 2; mt++) {
            #pragma unroll
            for (int half = 0; half < 2; half++) {
                int m  = bm + warpM * 32 + mt * 16 + g + half * 8;
                int b_ = m >> 11, s_ = m & 2047;
                uint2* dst = dstb + ((size_t)((b_ * HH + h) * SS + s_)) * 32;
                float o[4][4];
                #pragma unroll
                for (int nt = 0; nt < 4; nt++) {
                    float4 cs4 = *(const float4*)&g_rope[s_ * 32 + nt * 8 + 2 * t];
                    float x10 = acc[mt][nt][half*2],     x11 = acc[mt][nt][half*2+1];
                    float x20 = acc[mt][nt+4][half*2],   x21 = acc[mt][nt+4][half*2+1];
                    o[nt][0] = (x10 * cs4.x - x20 * cs4.y) * scl;
                    o[nt][1] = (x11 * cs4.z - x21 * cs4.w) * scl;
                    o[nt][2] = (x20 * cs4.x + x10 * cs4.y) * scl;
                    o[nt][3] = (x21 * cs4.z + x11 * cs4.w) * scl;
                }
                uint2 a0, a1;
                a0 = bsplit(o[0][0], o[0][1]); a1 = bsplit(o[1][0], o[1][1]);
                *(uint4*)(dst + 2*t)      = make_uint4(a0.x, a0.y, a1.x, a1.y);
                a0 = bsplit(o[2][0], o[2][1]); a1 = bsplit(o[3][0], o[3][1]);
                *(uint4*)(dst + 8 + 2*t)  = make_uint4(a0.x, a0.y, a1.x, a1.y);
                a0 = bsplit(o[0][2], o[0][3]); a1 = bsplit(o[1][2], o[1][3]);
                *(uint4*)(dst + 16 + 2*t) = make_uint4(a0.x, a0.y, a1.x, a1.y);
                a0 = bsplit(o[2][2], o[2][3]); a1 = bsplit(o[3][2], o[3][3]);
                *(uint4*)(dst + 24 + 2*t) = make_uint4(a0.x, a0.y, a1.x, a1.y);
            }
        }
    } else {
        const bool geven = !(g & 1);
        #pragma unroll
        for (int mt = 0; mt < 2; mt++) {
            int base = bm + warpM * 32 + mt * 16;
            int mp   = geven ? (base + g) : (base + g + 7);
            int b_   = mp >> 11;
            int sp   = (mp & 2047) >> 1;
            size_t rowb = (size_t)((b_ * HH + h) * 64);
            int sidx = SIDX(sp);
            #pragma unroll
            for (int nt = 0; nt < 8; nt++) {
                float c0 = acc[mt][nt][0], c1 = acc[mt][nt][1];
                float c2 = acc[mt][nt][2], c3 = acc[mt][nt][3];
                float p0 = __shfl_xor_sync(0xffffffffu, c0, 4);
                float p1 = __shfl_xor_sync(0xffffffffu, c1, 4);
                float p2 = __shfl_xor_sync(0xffffffffu, c2, 4);
                float p3 = __shfl_xor_sync(0xffffffffu, c3, 4);
                int d0 = nt * 8 + 2 * t;
                uint2 w0 = geven ? bsplit(c0, p0) : bsplit(p2, c2);
                uint2 w1 = geven ? bsplit(c1, p1) : bsplit(p3, c3);
                gVt[(rowb + d0)     * 1024 + sidx] = w0;
                gVt[(rowb + d0 + 1) * 1024 + sidx] = w1;
            }
        }
    }
}

// ---------------------------------------------------------------------------
// Flash attention (reverted to the 612us structure): BM=128, BN=64, 256 thr =
// 8 warps (16 q-rows each). Q fragments in registers; K/V double-buffered
// cp.async; one wait + one barrier per iter. Fixed-max softmax (m=0).
// ---------------------------------------------------------------------------
#define FST 40
#define FL_SMEM (4 * 64 * FST * (int)sizeof(uint2) + 2 * 64 * (int)sizeof(float))

__global__ __launch_bounds__(256, 2)
void flash_kernel(const float* __restrict__ mask, float* __restrict__ out)
{
    extern __shared__ uint2 smu[];
    uint2* Kst = smu;                           // 2 stages [64][FST]
    uint2* Vst = smu + 2 * 64 * FST;            // 2 stages [64][FST]
    float* mks = (float*)(smu + 4 * 64 * FST);  // 2 stages [64]
    const uint32_t sbase = smem_u32(smu);

    const int tid = threadIdx.x, lane = tid & 31, wid = tid >> 5;
    const int g = lane >> 2, t = lane & 3, wm = wid * 16;
    const int qt = blockIdx.x, bh = blockIdx.y, b = bh >> 4, h = bh & 15;

    const uint2* Qg = gQp + ((size_t)bh * SS + qt * 128) * 32;
    const uint2* Kg = gKp + (size_t)bh * SS * 32;
    const uint2* Vg = gVt + (size_t)bh * 64 * 1024;

    // Q fragments in registers, whole loop
    uint4 qf0[4], qf1[4];
    #pragma unroll
    for (int ks = 0; ks < 4; ks++) {
        qf0[ks] = *(const uint4*)(Qg + (wm + g)     * 32 + ks * 8 + 2 * t);
        qf1[ks] = *(const uint4*)(Qg + (wm + g + 8) * 32 + ks * 8 + 2 * t);
    }

    #define FL_ISSUE(kt, s) do { \
        uint32_t kb = sbase + (uint32_t)((s) * 64 * FST) * 8; \
        uint32_t vb = sbase + (uint32_t)((2 + (s)) * 64 * FST) * 8; \
        _Pragma("unroll") \
        for (int it = 0; it < 4; it++) { \
            int lin = tid + it * 256; \
            int row = lin >> 4, f = (lin & 15) * 2; \
            cp_async16(kb + (row * FST + f) * 8, Kg + (size_t)((kt)*64 + row) * 32 + f); \
            cp_async16(vb + (row * FST + f) * 8, Vg + (size_t)row * 1024 + (kt) * 32 + f); \
        } \
        if (tid < 16) \
            cp_async16(sbase + (uint32_t)(4 * 64 * FST) * 8 + (s) * 256 + tid * 16, \
                       mask + (size_t)b * SS + (kt) * 64 + tid * 4); \
        CP_COMMIT(); \
    } while (0)

    float lp0 = 0.f, lp1 = 0.f;
    float oc[8][4] = {};

    FL_ISSUE(0, 0);
    for (int kt = 0; kt < 32; kt++) {
        CP_WAIT0();
        __syncthreads();
        if (kt + 1 < 32) FL_ISSUE(kt + 1, (kt + 1) & 1);
        const uint2* Ks = Kst + (kt & 1) * 64 * FST;
        const uint2* Vs = Vst + (kt & 1) * 64 * FST;
        const float* mk = mks + (kt & 1) * 64;

        // S = Q K^T
        float sc[8][4] = {};
        #pragma unroll
        for (int ks = 0; ks < 4; ks++) {
            #pragma unroll
            for (int nt = 0; nt < 8; nt++) {
                uint4 bv = *(const uint4*)(Ks + (nt*8 + g) * FST + ks * 8 + 2 * t);
                mma3v(sc[nt], qf0[ks], qf1[ks], bv);
            }
        }

        // mask + exp (fixed max = 0), accumulate partial l
        #pragma unroll
        for (int nt = 0; nt < 8; nt++) {
            float mv0 = mk[nt*8 + 2*t], mv1 = mk[nt*8 + 2*t + 1];
            sc[nt][0] = __expf(sc[nt][0] + mv0); lp0 += sc[nt][0];
            sc[nt][1] = __expf(sc[nt][1] + mv1); lp0 += sc[nt][1];
            sc[nt][2] = __expf(sc[nt][2] + mv0); lp1 += sc[nt][2];
            sc[nt][3] = __expf(sc[nt][3] + mv1); lp1 += sc[nt][3];
        }

        // O += P V (P C-frag == A-frag)
        #pragma unroll
        for (int ks = 0; ks < 4; ks++) {
            uint2 pa0 = bsplit(sc[2*ks][0],   sc[2*ks][1]);
            uint2 pa1 = bsplit(sc[2*ks][2],   sc[2*ks][3]);
            uint2 pa2 = bsplit(sc[2*ks+1][0], sc[2*ks+1][1]);
            uint2 pa3 = bsplit(sc[2*ks+1][2], sc[2*ks+1][3]);
            uint4 a01 = make_uint4(pa0.x, pa0.y, pa2.x, pa2.y);
            uint4 a23 = make_uint4(pa1.x, pa1.y, pa3.x, pa3.y);
            #pragma unroll
            for (int dt = 0; dt < 8; dt++) {
                uint4 bv = *(const uint4*)(Vs + (dt*8 + g) * FST + ks * 8 + 2 * t);
                mma3v(oc[dt], a01, a23, bv);
            }
        }
    }

    lp0 += __shfl_xor_sync(0xffffffffu, lp0, 1);
    lp0 += __shfl_xor_sync(0xffffffffu, lp0, 2);
    lp1 += __shfl_xor_sync(0xffffffffu, lp1, 1);
    lp1 += __shfl_xor_sync(0xffffffffu, lp1, 2);
    float inv0 = 1.0f / lp0, inv1 = 1.0f / lp1;
    int s0g = qt * 128 + wm + g;
    #pragma unroll
    for (int dt = 0; dt < 8; dt++) {
        int d = dt * 8 + 2 * t;
        float* base = out + ((size_t)(b * SS + s0g)) * HIDD + h * 64 + d;
        *(float2*)base            = make_float2(oc[dt][0]*inv0, oc[dt][1]*inv0);
        *(float2*)(base + 8*HIDD) = make_float2(oc[dt][2]*inv1, oc[dt][3]*inv1);
    }
}

// ---------------------------------------------------------------------------
extern "C" void kernel_launch(void* const* d_in, const int* in_sizes, int n_in,
                              void* d_out, int out_size)
{
    const float* X    = (const float*)d_in[0];
    const float* mask = (const float*)d_in[1];
    const float* Wq   = (const float*)d_in[2];
    const float* Wk   = (const float*)d_in[3];
    const float* Wv   = (const float*)d_in[4];
    float* out = (float*)d_out;

    uint2* xp;
    cudaGetSymbolAddress((void**)&xp, gXp);

    rope_table_kernel<<<256, 256>>>();
    split_pack_kernel<<<4096, 256>>>(X, xp, BB*SS*HIDD/4);
    split_pack_w_kernel<<<dim3(1024, 3), 256>>>(Wq, Wk, Wv);

    cudaFuncSetAttribute(qkv_mma_kernel, cudaFuncAttributeMaxDynamicSharedMemorySize, QK_SMEM);
    qkv_mma_kernel<<<dim3(32, 8, 3), 256, QK_SMEM>>>();

    cudaFuncSetAttribute(flash_kernel, cudaFuncAttributeMaxDynamicSharedMemorySize, FL_SMEM);
    flash_kernel<<<dim3(SS/128, NBH), 256, FL_SMEM>>>(mask, out);
}